// round 3
// baseline (speedup 1.0000x reference)
#include <cuda_runtime.h>
#include <cstdint>

// N = 16777216, pred: float32 (N,2), target: int64 in reference (device layout
// detected in-kernel: int32 or int64), output: scalar float mean loss.
// Single-kernel HBM-streaming reduction: ~192 MB read, 4 B written.

static constexpr int N_ELEMS = 16777216;
static constexpr float INV_N = 1.0f / 16777216.0f;

// Cross-block reduction state. Zero at module load; the last block resets
// them each run, so every graph replay starts clean.
__device__ float g_partial;
__device__ unsigned int g_count;

__device__ __forceinline__ float elem_loss(float p0, float p1, bool z) {
    float a = z ? p0 : p1;   // correct-class prob
    float b = z ? p1 : p0;   // other prob
    float d = 1.0f - a;
    float sq = fmaf(d, d, b * b);
    return sq + (a < b ? 2.0f : 0.0f);
}

__global__ void __launch_bounds__(256) custom_loss_kernel(
    const float4* __restrict__ pred4,   // N/2 float4 (two (p0,p1) rows each)
    const void* __restrict__ tgt,
    float* __restrict__ out,
    int noct)                            // N/8 groups of 8 elements
{
    // ---- in-kernel layout detection (uniform per block) ----
    // First 64 odd 32-bit words: all zero if targets are int64 (hi words of
    // 0/1 values); ~half nonzero if targets are int32 0/1. In-bounds either way.
    __shared__ int s_i32;
    if (threadIdx.x == 0) s_i32 = 0;
    __syncthreads();
    if (threadIdx.x < 64) {
        if (((const int*)tgt)[2 * threadIdx.x + 1] != 0) s_i32 = 1;
    }
    __syncthreads();
    const bool i32 = (s_i32 != 0);

    const int4* __restrict__ t32 = (const int4*)tgt;
    const ulonglong2* __restrict__ t64 = (const ulonglong2*)tgt;

    float acc = 0.0f;
    int idx = blockIdx.x * blockDim.x + threadIdx.x;
    int stride = gridDim.x * blockDim.x;

    for (int i = idx; i < noct; i += stride) {
        const float4* p = pred4 + 4 * i;
        float4 pa = __ldg(p);        // elems 8i+0,1
        float4 pb = __ldg(p + 1);    // elems 8i+2,3
        float4 pc = __ldg(p + 2);    // elems 8i+4,5
        float4 pd = __ldg(p + 3);    // elems 8i+6,7

        bool z0, z1, z2, z3, z4, z5, z6, z7;
        if (i32) {
            int4 ta = __ldg(t32 + 2 * i);
            int4 tb = __ldg(t32 + 2 * i + 1);
            z0 = (ta.x == 0); z1 = (ta.y == 0); z2 = (ta.z == 0); z3 = (ta.w == 0);
            z4 = (tb.x == 0); z5 = (tb.y == 0); z6 = (tb.z == 0); z7 = (tb.w == 0);
        } else {
            ulonglong2 ua = __ldg(t64 + 4 * i);
            ulonglong2 ub = __ldg(t64 + 4 * i + 1);
            ulonglong2 uc = __ldg(t64 + 4 * i + 2);
            ulonglong2 ud = __ldg(t64 + 4 * i + 3);
            z0 = (ua.x == 0ULL); z1 = (ua.y == 0ULL);
            z2 = (ub.x == 0ULL); z3 = (ub.y == 0ULL);
            z4 = (uc.x == 0ULL); z5 = (uc.y == 0ULL);
            z6 = (ud.x == 0ULL); z7 = (ud.y == 0ULL);
        }

        acc += elem_loss(pa.x, pa.y, z0);
        acc += elem_loss(pa.z, pa.w, z1);
        acc += elem_loss(pb.x, pb.y, z2);
        acc += elem_loss(pb.z, pb.w, z3);
        acc += elem_loss(pc.x, pc.y, z4);
        acc += elem_loss(pc.z, pc.w, z5);
        acc += elem_loss(pd.x, pd.y, z6);
        acc += elem_loss(pd.z, pd.w, z7);
    }

    // ---- intra-block reduce ----
    #pragma unroll
    for (int o = 16; o > 0; o >>= 1)
        acc += __shfl_xor_sync(0xFFFFFFFFu, acc, o);

    __shared__ float smem[8];  // 256 threads = 8 warps
    int lane = threadIdx.x & 31;
    int warp = threadIdx.x >> 5;
    if (lane == 0) smem[warp] = acc;
    __syncthreads();

    if (threadIdx.x == 0) {
        float bsum = 0.0f;
        #pragma unroll
        for (int w = 0; w < 8; w++) bsum += smem[w];

        // ---- cross-block: accumulate, last block finalizes + resets ----
        atomicAdd(&g_partial, bsum * INV_N);
        __threadfence();
        unsigned prev = atomicAdd(&g_count, 1u);
        if (prev == gridDim.x - 1) {
            // atomicExch reads the coherent total AND resets for next replay
            float total = atomicExch(&g_partial, 0.0f);
            out[0] = total;
            atomicExch(&g_count, 0u);
        }
    }
}

extern "C" void kernel_launch(void* const* d_in, const int* in_sizes, int n_in,
                              void* d_out, int out_size) {
    const float4* pred4 = (const float4*)d_in[0];
    const void* tgt = d_in[1];
    float* out = (float*)d_out;

    int noct = N_ELEMS / 8;   // 2097152
    int blocks = 148 * 16;    // 2368 blocks x 256 threads
    custom_loss_kernel<<<blocks, 256>>>(pred4, tgt, out, noct);
}

// round 4
// speedup vs baseline: 1.0438x; 1.0438x over previous
#include <cuda_runtime.h>
#include <cstdint>

// N = 16777216, pred: float32 (N,2), target: int64 in reference (device layout
// detected in-kernel: int32 or int64), output: scalar float mean loss.
// Single-kernel HBM-streaming reduction: ~201 MB read, 4 B written.
// All loads warp-coalesced via interleaved (column) striding.

static constexpr int N_ELEMS = 16777216;
static constexpr float INV_N = 1.0f / 16777216.0f;

static constexpr int BLOCKS  = 2048;
static constexpr int THREADS = 256;
static constexpr int TOTAL   = BLOCKS * THREADS;          // 2^19
static constexpr int NPAIRS  = N_ELEMS / 2;               // 2^23
static constexpr int ITERS   = NPAIRS / TOTAL;            // 16, exact

// Cross-block reduction state. Zero at module load; last block resets each
// run so every graph replay starts clean.
__device__ float g_partial;
__device__ unsigned int g_count;

__device__ __forceinline__ float elem_loss(float p0, float p1, bool z) {
    float a = z ? p0 : p1;   // correct-class prob
    float b = z ? p1 : p0;   // other prob
    float d = 1.0f - a;
    float sq = fmaf(d, d, b * b);
    return sq + (a < b ? 2.0f : 0.0f);
}

__global__ void __launch_bounds__(THREADS) custom_loss_kernel(
    const float4* __restrict__ pred4,   // NPAIRS float4 ((p0,p1) x2... no: one pair per float4? )
    const void* __restrict__ tgt,
    float* __restrict__ out)
{
    // pred4[i] = (p0[2i], p1[2i], p0[2i+1], p1[2i+1]) — two rows per float4.

    // ---- in-kernel layout detection (uniform per block) ----
    // Odd 32-bit words among the first 128 words: all zero iff targets are
    // int64 0/1 (their high words); ~half nonzero if int32. In-bounds always.
    __shared__ int s_i32;
    if (threadIdx.x == 0) s_i32 = 0;
    __syncthreads();
    if (threadIdx.x < 64) {
        if (((const int*)tgt)[2 * threadIdx.x + 1] != 0) s_i32 = 1;
    }
    __syncthreads();
    const bool i32 = (s_i32 != 0);

    const int gid = blockIdx.x * THREADS + threadIdx.x;

    float acc = 0.0f;

    if (i32) {
        const int2* __restrict__ t2 = (const int2*)tgt;   // 2 targets per int2
        #pragma unroll 4
        for (int k = 0; k < ITERS; k++) {
            int i = gid + k * TOTAL;
            float4 p = __ldg(pred4 + i);
            int2 t = __ldg(t2 + i);
            acc += elem_loss(p.x, p.y, t.x == 0);
            acc += elem_loss(p.z, p.w, t.y == 0);
        }
    } else {
        const ulonglong2* __restrict__ t2 = (const ulonglong2*)tgt;
        #pragma unroll 4
        for (int k = 0; k < ITERS; k++) {
            int i = gid + k * TOTAL;
            float4 p = __ldg(pred4 + i);
            ulonglong2 t = __ldg(t2 + i);
            acc += elem_loss(p.x, p.y, t.x == 0ULL);
            acc += elem_loss(p.z, p.w, t.y == 0ULL);
        }
    }

    // ---- intra-block reduce ----
    #pragma unroll
    for (int o = 16; o > 0; o >>= 1)
        acc += __shfl_xor_sync(0xFFFFFFFFu, acc, o);

    __shared__ float smem[THREADS / 32];
    int lane = threadIdx.x & 31;
    int warp = threadIdx.x >> 5;
    if (lane == 0) smem[warp] = acc;
    __syncthreads();

    if (threadIdx.x == 0) {
        float bsum = 0.0f;
        #pragma unroll
        for (int w = 0; w < THREADS / 32; w++) bsum += smem[w];

        // ---- cross-block: accumulate, last block finalizes + resets ----
        atomicAdd(&g_partial, bsum * INV_N);
        __threadfence();
        unsigned prev = atomicAdd(&g_count, 1u);
        if (prev == gridDim.x - 1) {
            float total = atomicExch(&g_partial, 0.0f);  // read + reset
            out[0] = total;
            atomicExch(&g_count, 0u);
        }
    }
}

extern "C" void kernel_launch(void* const* d_in, const int* in_sizes, int n_in,
                              void* d_out, int out_size) {
    const float4* pred4 = (const float4*)d_in[0];
    const void* tgt = d_in[1];
    float* out = (float*)d_out;

    custom_loss_kernel<<<BLOCKS, THREADS>>>(pred4, tgt, out);
}

// round 5
// speedup vs baseline: 1.0580x; 1.0136x over previous
#include <cuda_runtime.h>
#include <cstdint>

// N = 16777216, pred: float32 (N,2), target: int64 in reference (device layout
// detected in-kernel: int32 or int64), output: scalar float mean loss.
// Single persistent-wave HBM-streaming reduction: ~192 MB read, 4 B written.
// 1184 blocks = 148 SMs x 8 resident blocks -> exactly one wave, no tail.

static constexpr int N_ELEMS = 16777216;
static constexpr float INV_N = 1.0f / 16777216.0f;

static constexpr int BLOCKS  = 148 * 8;                   // 1184 = one full wave
static constexpr int THREADS = 256;
static constexpr int TOTAL   = BLOCKS * THREADS;          // 303104
static constexpr int NPAIRS  = N_ELEMS / 2;               // 8388608 (27.68 iters/thread)

// Cross-block reduction state. Zero at module load; last block resets each
// run so every graph replay starts clean.
__device__ float g_partial;
__device__ unsigned int g_count;

__device__ __forceinline__ float elem_loss(float p0, float p1, bool z) {
    float a = z ? p0 : p1;   // correct-class prob
    float b = z ? p1 : p0;   // other prob
    float d = 1.0f - a;
    float sq = fmaf(d, d, b * b);
    return sq + (a < b ? 2.0f : 0.0f);
}

__global__ void __launch_bounds__(THREADS) custom_loss_kernel(
    const float4* __restrict__ pred4,   // pred4[i] = rows 2i and 2i+1
    const void* __restrict__ tgt,
    float* __restrict__ out)
{
    // ---- in-kernel layout detection (uniform per block) ----
    // Odd 32-bit words among the first 128 words: all zero iff targets are
    // int64 0/1 (their high words); ~half nonzero if int32. In-bounds always.
    __shared__ int s_i32;
    if (threadIdx.x == 0) s_i32 = 0;
    __syncthreads();
    if (threadIdx.x < 64) {
        if (((const int*)tgt)[2 * threadIdx.x + 1] != 0) s_i32 = 1;
    }
    __syncthreads();
    const bool i32 = (s_i32 != 0);

    const int gid = blockIdx.x * THREADS + threadIdx.x;

    float acc = 0.0f;

    if (i32) {
        const int2* __restrict__ t2 = (const int2*)tgt;   // 2 targets per int2
        #pragma unroll 4
        for (int i = gid; i < NPAIRS; i += TOTAL) {
            float4 p = __ldg(pred4 + i);
            int2 t = __ldg(t2 + i);
            acc += elem_loss(p.x, p.y, t.x == 0);
            acc += elem_loss(p.z, p.w, t.y == 0);
        }
    } else {
        const ulonglong2* __restrict__ t2 = (const ulonglong2*)tgt;
        #pragma unroll 4
        for (int i = gid; i < NPAIRS; i += TOTAL) {
            float4 p = __ldg(pred4 + i);
            ulonglong2 t = __ldg(t2 + i);
            acc += elem_loss(p.x, p.y, t.x == 0ULL);
            acc += elem_loss(p.z, p.w, t.y == 0ULL);
        }
    }

    // ---- intra-block reduce ----
    #pragma unroll
    for (int o = 16; o > 0; o >>= 1)
        acc += __shfl_xor_sync(0xFFFFFFFFu, acc, o);

    __shared__ float smem[THREADS / 32];
    int lane = threadIdx.x & 31;
    int warp = threadIdx.x >> 5;
    if (lane == 0) smem[warp] = acc;
    __syncthreads();

    if (threadIdx.x == 0) {
        float bsum = 0.0f;
        #pragma unroll
        for (int w = 0; w < THREADS / 32; w++) bsum += smem[w];

        // ---- cross-block: accumulate, last block finalizes + resets ----
        atomicAdd(&g_partial, bsum * INV_N);
        __threadfence();
        unsigned prev = atomicAdd(&g_count, 1u);
        if (prev == gridDim.x - 1) {
            float total = atomicExch(&g_partial, 0.0f);  // read + reset
            out[0] = total;
            atomicExch(&g_count, 0u);
        }
    }
}

extern "C" void kernel_launch(void* const* d_in, const int* in_sizes, int n_in,
                              void* d_out, int out_size) {
    const float4* pred4 = (const float4*)d_in[0];
    const void* tgt = d_in[1];
    float* out = (float*)d_out;

    custom_loss_kernel<<<BLOCKS, THREADS>>>(pred4, tgt, out);
}